// round 16
// baseline (speedup 1.0000x reference)
#include <cuda_runtime.h>
#include <cuda_bf16.h>
#include <cstdint>

#define BB 512
#define LL 512
#define NN 128
#define WP 68     // emission-stage pitch (floats): 68*2c %32 = 8c -> conflict-free reads

__device__ float g_norm[BB];
__device__ float g_path[BB];

__device__ __forceinline__ uint32_t bfpack(float lo, float hi) {
    uint32_t d;
    asm("cvt.rn.bf16x2.f32 %0, %1, %2;" : "=r"(d) : "f"(hi), "f"(lo));
    return d;
}
__device__ __forceinline__ float frcp(float x) {
    float r;
    asm("rcp.approx.f32 %0, %1;" : "=f"(r) : "f"(x));
    return r;
}
__device__ __forceinline__ uint32_t movm(uint32_t x) {
    uint32_t d;
    asm("movmatrix.sync.aligned.m8n8.trans.b16 %0, %1;" : "=r"(d) : "r"(x));
    return d;
}
__device__ __forceinline__ void mma16816(float* d,
                                         uint32_t a0, uint32_t a1, uint32_t a2, uint32_t a3,
                                         uint32_t b0, uint32_t b1) {
    asm volatile("mma.sync.aligned.m16n8k16.row.col.f32.bf16.bf16.f32 "
                 "{%0,%1,%2,%3},{%4,%5,%6,%7},{%8,%9},{%0,%1,%2,%3};"
                 : "+f"(d[0]), "+f"(d[1]), "+f"(d[2]), "+f"(d[3])
                 : "r"(a0), "r"(a1), "r"(a2), "r"(a3), "r"(b0), "r"(b1));
}

// ---------------------------------------------------------------------------
// Forward: 64 blocks x 64 threads (2 warps) = one group of 8 batches per SM.
// Warp w owns m-tiles 4w..4w+3 (states 64w..64w+63) for ALL 8 batches:
// 32 HMMA/step, A = E^T half resident (128 regs). Next-step B frags: own 4
// k-tiles stay in registers (movmatrix); remote 4 exchanged via smem across
// a 2-warp __syncthreads. Emission: coalesced LDG 2 steps ahead, exp'd into
// a warp-local smem stage. Branch-free epilogue. One barrier per step.
// ---------------------------------------------------------------------------
__global__ __launch_bounds__(64, 1)
void crf_forward(const float* __restrict__ em,
                 const float* __restrict__ mask,
                 const float* __restrict__ start,
                 const float* __restrict__ trans) {
    __shared__ uint2 qx[2][2][4][32];      // [parity][srcwarp][mi][lane]
    __shared__ float invsh[2][8];          // [parity][batch]
    __shared__ float msh[2][8];            // [parity][batch]
    __shared__ float est[2][2][8][WP];     // [parity][warp][batch][local state]
    __shared__ float csh[8];
    __shared__ float ssum[2][8];

    const int tid  = threadIdx.x;
    const int w    = tid >> 5;             // 0 or 1
    const int ow   = 1 - w;
    const int lane = tid & 31;
    const int r    = lane >> 2;
    const int c    = lane & 3;
    const int bA   = 2 * c, bB = bA + 1;
    const int b0g  = blockIdx.x * 8;
    const bool w0r0 = (w == 0) && (r == 0);

    // this warp's states: S[mi][h] global, sl = local (0..63)
    int S[4][2];
#pragma unroll
    for (int mi = 0; mi < 4; mi++) {
        S[mi][0] = 16 * (4 * w + mi) + r;
        S[mi][1] = S[mi][0] + 8;
    }

    // ---- A fragments: A[j][i] = exp(trans[i*128+j]) (same as validated R14) ----
    uint32_t Af[4][8][4];
#pragma unroll
    for (int mi = 0; mi < 4; mi++) {
        const int j0 = S[mi][0], j1 = S[mi][1];
#pragma unroll
        for (int kt = 0; kt < 8; kt++) {
            const int i0 = 16 * kt + 2 * c;
            Af[mi][kt][0] = bfpack(__expf(trans[(i0)     * NN + j0]),
                                   __expf(trans[(i0 + 1) * NN + j0]));
            Af[mi][kt][1] = bfpack(__expf(trans[(i0)     * NN + j1]),
                                   __expf(trans[(i0 + 1) * NN + j1]));
            Af[mi][kt][2] = bfpack(__expf(trans[(i0 + 8) * NN + j0]),
                                   __expf(trans[(i0 + 9) * NN + j0]));
            Af[mi][kt][3] = bfpack(__expf(trans[(i0 + 8) * NN + j1]),
                                   __expf(trans[(i0 + 9) * NN + j1]));
        }
    }

    // coalesced emission role: batch lb, 16 contiguous floats at 64w + 16*qd
    const int lb = lane >> 2, qd = lane & 3;
    const float* eml = em + (size_t)(b0g + lb) * (LL * NN) + 64 * w + 16 * qd;
    const float* mkl = mask + (size_t)(b0g + lane) * LL;   // lanes 0-7 of warp 0

    float Lr_A = 0.f, Lr_B = 0.f;
    float qprev[4][2][2];          // [mi][h][batch(A/B)]
    uint2 Bl[4];                   // own next-step B frags (k-tiles 4w+mi)
    float4 vS[4];                  // em[t+1] raw (staged next step)
    float  mvS = 1.0f;

    // ================= init t = 0 =================
    {
        float s0[4][2][2];
        const size_t ebA = (size_t)(b0g + bA) * (LL * NN);
        const size_t ebB = (size_t)(b0g + bB) * (LL * NN);
#pragma unroll
        for (int mi = 0; mi < 4; mi++)
#pragma unroll
            for (int h = 0; h < 2; h++) {
                const int s = S[mi][h];
                const float st = start[s];
                s0[mi][h][0] = st + em[ebA + s];
                s0[mi][h][1] = st + em[ebB + s];
            }
        if (w0r0) { csh[bA] = s0[0][0][0]; csh[bB] = s0[0][0][1]; }
        __syncthreads();
        const float cA = csh[bA], cB = csh[bB];
        Lr_A = cA; Lr_B = cB;
#pragma unroll
        for (int mi = 0; mi < 4; mi++)
#pragma unroll
            for (int h = 0; h < 2; h++) {
                qprev[mi][h][0] = __expf(s0[mi][h][0] - cA);
                qprev[mi][h][1] = __expf(s0[mi][h][1] - cB);
            }
        if (w0r0) {
            invsh[1][bA] = frcp(qprev[0][0][0]);
            invsh[1][bB] = frcp(qprev[0][0][1]);
        }
#pragma unroll
        for (int mi = 0; mi < 4; mi++) {
            uint32_t u0 = bfpack(qprev[mi][0][0], qprev[mi][0][1]);
            uint32_t u1 = bfpack(qprev[mi][1][0], qprev[mi][1][1]);
            Bl[mi] = make_uint2(movm(u0), movm(u1));
            qx[1][w][mi][lane] = Bl[mi];
        }
        // stage exp(em[1]); preload em[2]
        float4 e1[4];
#pragma unroll
        for (int i = 0; i < 4; i++) e1[i] = *(const float4*)&eml[(size_t)1 * NN + 4 * i];
#pragma unroll
        for (int i = 0; i < 4; i++) {
            est[1][w][lb][16 * qd + 4 * i + 0] = __expf(e1[i].x);
            est[1][w][lb][16 * qd + 4 * i + 1] = __expf(e1[i].y);
            est[1][w][lb][16 * qd + 4 * i + 2] = __expf(e1[i].z);
            est[1][w][lb][16 * qd + 4 * i + 3] = __expf(e1[i].w);
        }
#pragma unroll
        for (int i = 0; i < 4; i++) vS[i] = *(const float4*)&eml[(size_t)2 * NN + 4 * i];
        if (w == 0 && lane < 8) {
            msh[1][lane] = mkl[1];
            mvS = mkl[2];
        }
        __syncthreads();
    }

    // ================= recurrence =================
    for (int t = 1; t < LL; t++) {
        const int pr = t & 1, pw = pr ^ 1;

        // ---- remote B frags + inv + mask + et (written before last bar) ----
        uint2 bqr[4];
#pragma unroll
        for (int mi = 0; mi < 4; mi++) bqr[mi] = qx[pr][ow][mi][lane];
        const float invA = invsh[pr][bA];
        const float invB = invsh[pr][bB];
        const float mkA = msh[pr][bA];
        const float mkB = msh[pr][bB];

        float sc[4][2][2];
#pragma unroll
        for (int mi = 0; mi < 4; mi++)
#pragma unroll
            for (int h = 0; h < 2; h++) {
                const int sl = 16 * mi + r + 8 * h;
                sc[mi][h][0] = est[pr][w][bA][sl] * invA;
                sc[mi][h][1] = est[pr][w][bB][sl] * invB;
            }

        // ---- stage exp(em[t+1]) from regs; LDG em[t+2] clamped ----
#pragma unroll
        for (int i = 0; i < 4; i++) {
            est[pw][w][lb][16 * qd + 4 * i + 0] = __expf(vS[i].x);
            est[pw][w][lb][16 * qd + 4 * i + 1] = __expf(vS[i].y);
            est[pw][w][lb][16 * qd + 4 * i + 2] = __expf(vS[i].z);
            est[pw][w][lb][16 * qd + 4 * i + 3] = __expf(vS[i].w);
        }
        if (w == 0 && lane < 8) msh[pw][lane] = mvS;
        const int tC = (t + 2 < LL) ? (t + 2) : (LL - 1);
#pragma unroll
        for (int i = 0; i < 4; i++)
            vS[i] = *(const float4*)&eml[(size_t)tC * NN + 4 * i];
        if (w == 0 && lane < 8) mvS = mkl[tC];

        // ---- assemble bq: own k-tiles from regs, remote from smem ----
        uint2 bq[8];
#pragma unroll
        for (int mi = 0; mi < 4; mi++) {
            bq[4 * w + mi]  = Bl[mi];
            bq[4 * ow + mi] = bqr[mi];
        }

        // ---- MMA: 8 chains of depth 4 (even/odd k per m-tile) ----
        float accE[4][4], accO[4][4];
#pragma unroll
        for (int mi = 0; mi < 4; mi++)
#pragma unroll
            for (int i = 0; i < 4; i++) { accE[mi][i] = 0.f; accO[mi][i] = 0.f; }
#pragma unroll
        for (int kt = 0; kt < 8; kt += 2) {
#pragma unroll
            for (int mi = 0; mi < 4; mi++) {
                mma16816(accE[mi], Af[mi][kt][0], Af[mi][kt][1], Af[mi][kt][2], Af[mi][kt][3],
                         bq[kt].x, bq[kt].y);
                mma16816(accO[mi], Af[mi][kt+1][0], Af[mi][kt+1][1], Af[mi][kt+1][2], Af[mi][kt+1][3],
                         bq[kt+1].x, bq[kt+1].y);
            }
        }

        // ---- branch-free epilogue ----
        float qn[4][2][2];
        bool fr = false;
#pragma unroll
        for (int mi = 0; mi < 4; mi++) {
            float qc0 = (accE[mi][0] + accO[mi][0]) * sc[mi][0][0];
            float qc1 = (accE[mi][1] + accO[mi][1]) * sc[mi][0][1];
            float qc2 = (accE[mi][2] + accO[mi][2]) * sc[mi][1][0];
            float qc3 = (accE[mi][3] + accO[mi][3]) * sc[mi][1][1];
            float qo0 = qprev[mi][0][0] * invA;
            float qo1 = qprev[mi][0][1] * invB;
            float qo2 = qprev[mi][1][0] * invA;
            float qo3 = qprev[mi][1][1] * invB;
            qn[mi][0][0] = (mkA != 0.0f) ? qc0 : qo0;
            qn[mi][0][1] = (mkB != 0.0f) ? qc1 : qo1;
            qn[mi][1][0] = (mkA != 0.0f) ? qc2 : qo2;
            qn[mi][1][1] = (mkB != 0.0f) ? qc3 : qo3;
        }
        fr = ((mkA != 0.0f) && (mkA != 1.0f)) || ((mkB != 0.0f) && (mkB != 1.0f));
        if (__any_sync(0xffffffffu, fr)) {   // exact fractional-mask fallback
#pragma unroll
            for (int mi = 0; mi < 4; mi++)
#pragma unroll
                for (int h = 0; h < 2; h++) {
                    float qcv0 = (accE[mi][2*h] + accO[mi][2*h]) * sc[mi][h][0];
                    float qcv1 = (accE[mi][2*h+1] + accO[mi][2*h+1]) * sc[mi][h][1];
                    qn[mi][h][0] = __expf(mkA * __logf(qcv0) +
                                          (1.f - mkA) * __logf(qprev[mi][h][0] * invA));
                    qn[mi][h][1] = __expf(mkB * __logf(qcv1) +
                                          (1.f - mkB) * __logf(qprev[mi][h][1] * invB));
                }
        }

        // ---- pack + exchange frags FIRST (they gate the other warp) ----
#pragma unroll
        for (int mi = 0; mi < 4; mi++) {
            uint32_t u0 = bfpack(qn[mi][0][0], qn[mi][0][1]);
            uint32_t u1 = bfpack(qn[mi][1][0], qn[mi][1][1]);
            Bl[mi] = make_uint2(movm(u0), movm(u1));
            qx[pw][w][mi][lane] = Bl[mi];
#pragma unroll
            for (int h = 0; h < 2; h++) {
                qprev[mi][h][0] = qn[mi][h][0];
                qprev[mi][h][1] = qn[mi][h][1];
            }
        }

        // ---- log-offset + next inverse ----
        Lr_A -= __logf(invA);
        Lr_B -= __logf(invB);
        if (w0r0) {
            invsh[pw][bA] = frcp(qn[0][0][0]);
            invsh[pw][bB] = frcp(qn[0][0][1]);
        }
        __syncthreads();
    }

    // ================= final: normalizer = L + log(sum q) =================
    float sA = 0.f, sB = 0.f;
#pragma unroll
    for (int mi = 0; mi < 4; mi++)
#pragma unroll
        for (int h = 0; h < 2; h++) { sA += qprev[mi][h][0]; sB += qprev[mi][h][1]; }
#pragma unroll
    for (int o = 4; o <= 16; o <<= 1) {
        sA += __shfl_xor_sync(0xffffffffu, sA, o);
        sB += __shfl_xor_sync(0xffffffffu, sB, o);
    }
    if (r == 0) { ssum[w][bA] = sA; ssum[w][bB] = sB; }
    __syncthreads();
    if (w0r0) {
        g_norm[b0g + bA] = Lr_A + __logf(ssum[0][bA] + ssum[1][bA]);
        g_norm[b0g + bB] = Lr_B + __logf(ssum[0][bB] + ssum[1][bB]);
    }
}

// ---------------------------------------------------------------------------
// Path score. One block (128 threads) per batch.
// ---------------------------------------------------------------------------
__global__ __launch_bounds__(128)
void crf_path(const float* __restrict__ em,
              const int*   __restrict__ tgt,
              const float* __restrict__ mask,
              const float* __restrict__ start,
              const float* __restrict__ trans) {
    const int bb = blockIdx.x;
    const int tid = threadIdx.x;
    __shared__ float red[128];

    const size_t embase = (size_t)bb * LL * NN;
    float s = 0.0f;
    for (int t = tid; t < LL; t += 128) {
        if (t == 0) {
            int t0 = tgt[bb * LL];
            s += start[t0] + em[embase + t0];
        } else {
            int prev = tgt[bb * LL + t - 1];
            int cur  = tgt[bb * LL + t];
            s += mask[bb * LL + t] *
                 (trans[prev * NN + cur] + em[embase + (size_t)t * NN + cur]);
        }
    }
    red[tid] = s;
    __syncthreads();
#pragma unroll
    for (int o = 64; o; o >>= 1) {
        if (tid < o) red[tid] += red[tid + o];
        __syncthreads();
    }
    if (tid == 0) g_path[bb] = red[0];
}

// ---------------------------------------------------------------------------
// mean(normalizer - path)
// ---------------------------------------------------------------------------
__global__ __launch_bounds__(512)
void crf_final(float* __restrict__ out) {
    const int tid = threadIdx.x;
    __shared__ float wsum[16];
    float v = g_norm[tid] - g_path[tid];
#pragma unroll
    for (int o = 16; o; o >>= 1) v += __shfl_xor_sync(0xffffffffu, v, o);
    if ((tid & 31) == 0) wsum[tid >> 5] = v;
    __syncthreads();
    if (tid < 32) {
        float x = (tid < 16) ? wsum[tid] : 0.0f;
#pragma unroll
        for (int o = 8; o; o >>= 1) x += __shfl_xor_sync(0xffffffffu, x, o);
        if (tid == 0) out[0] = x * (1.0f / (float)BB);
    }
}

// ---------------------------------------------------------------------------
// Launch
// ---------------------------------------------------------------------------
extern "C" void kernel_launch(void* const* d_in, const int* in_sizes, int n_in,
                              void* d_out, int out_size) {
    const float* emission    = (const float*)d_in[0];
    const int*   target      = (const int*)  d_in[1];
    const float* mask        = (const float*)d_in[2];
    const float* start_trans = (const float*)d_in[3];
    const float* trans       = (const float*)d_in[4];
    float* out = (float*)d_out;

    crf_forward<<<64, 64>>>(emission, mask, start_trans, trans);
    crf_path<<<BB, 128>>>(emission, target, mask, start_trans, trans);
    crf_final<<<1, 512>>>(out);
}